// round 6
// baseline (speedup 1.0000x reference)
#include <cuda_runtime.h>
#include <cuda_bf16.h>
#include <limits.h>

#define N_NODES   100000
#define N_EDGES   1600000
#define ETOT      (N_EDGES + N_NODES)
#define F_IN      100
#define HEADS     3
#define HEAD_DIM  64
#define HIDDEN    192
#define NUM_GRAPHS 128
#define NUM_CLASSES 2
#define NEG_ATT   0.2f
#define NEG_ACT   0.01f
#define SCAN_T    1024

// ---------------- scratch (device globals; no allocations allowed) ----------
__device__ __align__(16) float g_h   [(size_t)N_NODES * HIDDEN];   // 76.8 MB
__device__ __align__(16) float g_out [(size_t)N_NODES * HIDDEN];   // 76.8 MB
__device__ __align__(16) float g_asrc[N_NODES * HEADS];
__device__ __align__(16) float g_adst[N_NODES * HEADS];
__device__ __align__(16) int   g_mkey[N_NODES * HEADS];            // encoded float max
__device__ __align__(16) float g_den [N_NODES * HEADS];
__device__ __align__(16) float g_e   [(size_t)ETOT * HEADS];       // 20.4 MB
__device__ __align__(16) int   g_src [N_EDGES];
__device__ __align__(16) int   g_dst [N_EDGES];
__device__ __align__(16) int   g_pool[NUM_GRAPHS * HIDDEN];        // encoded float max
// CSR structures
__device__ __align__(16) int   g_deg [N_NODES];
__device__ __align__(16) int   g_cnt [N_NODES];
__device__ __align__(16) int   g_row [N_NODES + 1];
__device__ __align__(16) int   g_ecol[ETOT];   // src node per CSR slot
__device__ __align__(16) int   g_eid [ETOT];   // edge id per CSR slot

// monotone float<->int encoding so atomicMax(int) == float max (finite vals)
__device__ __forceinline__ int fenc(float f) {
    int i = __float_as_int(f);
    return i >= 0 ? i : (i ^ 0x7FFFFFFF);
}
__device__ __forceinline__ float fdec(int i) {
    return __int_as_float(i >= 0 ? i : (i ^ 0x7FFFFFFF));
}
__device__ __forceinline__ int clampN(int v) {
    return (v < 0) ? 0 : ((v >= N_NODES) ? N_NODES - 1 : v);
}

// ---------------- K0: init + edge index load (int32 inputs!) -----------------
__global__ void k_init(const int* __restrict__ ei) {
    int i = blockIdx.x * blockDim.x + threadIdx.x;
    if (i < N_NODES * HEADS) { g_mkey[i] = INT_MIN; g_den[i] = 0.0f; }
    if (i < N_NODES) { g_deg[i] = 0; g_cnt[i] = 0; }
    if (i < NUM_GRAPHS * HIDDEN) g_pool[i] = INT_MIN;
    if (i < N_EDGES) {
        g_src[i] = clampN(ei[i]);
        g_dst[i] = clampN(ei[N_EDGES + i]);
    }
}

// ---------------- K1: h = x @ W, fused a_src/a_dst epilogue ------------------
// block: 48 x 8 threads; block covers 32 rows; thread = 4 cols (float4) x 4 rows
__global__ __launch_bounds__(384) void k_gemm(
    const float* __restrict__ x, const float* __restrict__ W,
    const float* __restrict__ att_src, const float* __restrict__ att_dst)
{
    __shared__ float xs[32][F_IN + 4];
    __shared__ float sa_s[32][HEADS];
    __shared__ float sa_d[32][HEADS];

    const int tx = threadIdx.x;           // 0..47  (col group)
    const int ty = threadIdx.y;           // 0..7   (row group of 4)
    const int tid = ty * 48 + tx;
    const int row0 = blockIdx.x * 32;

    for (int t = tid; t < 32 * F_IN; t += 384) {
        int r = t / F_IN, k = t - r * F_IN;
        xs[r][k] = x[(size_t)(row0 + r) * F_IN + k];
    }
    if (tid < 96)  ((float*)sa_s)[tid] = 0.0f;
    else if (tid < 192) ((float*)sa_d)[tid - 96] = 0.0f;
    __syncthreads();

    float4 acc0 = {0,0,0,0}, acc1 = {0,0,0,0}, acc2 = {0,0,0,0}, acc3 = {0,0,0,0};
    const int r0 = ty * 4;
    const float4* W4 = (const float4*)W;  // [F_IN][48] float4

    #pragma unroll 4
    for (int k = 0; k < F_IN; k++) {
        float4 w = __ldg(&W4[k * 48 + tx]);
        float x0 = xs[r0 + 0][k], x1 = xs[r0 + 1][k], x2 = xs[r0 + 2][k], x3 = xs[r0 + 3][k];
        acc0.x += x0 * w.x; acc0.y += x0 * w.y; acc0.z += x0 * w.z; acc0.w += x0 * w.w;
        acc1.x += x1 * w.x; acc1.y += x1 * w.y; acc1.z += x1 * w.z; acc1.w += x1 * w.w;
        acc2.x += x2 * w.x; acc2.y += x2 * w.y; acc2.z += x2 * w.z; acc2.w += x2 * w.w;
        acc3.x += x3 * w.x; acc3.y += x3 * w.y; acc3.z += x3 * w.z; acc3.w += x3 * w.w;
    }

    float4* H4 = (float4*)g_h;
    H4[(size_t)(row0 + r0 + 0) * 48 + tx] = acc0;
    H4[(size_t)(row0 + r0 + 1) * 48 + tx] = acc1;
    H4[(size_t)(row0 + r0 + 2) * 48 + tx] = acc2;
    H4[(size_t)(row0 + r0 + 3) * 48 + tx] = acc3;

    const int head = tx >> 4;
    float4 as = __ldg(&((const float4*)att_src)[tx]);
    float4 ad = __ldg(&((const float4*)att_dst)[tx]);
    float ps, pd;
    ps = acc0.x*as.x + acc0.y*as.y + acc0.z*as.z + acc0.w*as.w;
    pd = acc0.x*ad.x + acc0.y*ad.y + acc0.z*ad.z + acc0.w*ad.w;
    atomicAdd(&sa_s[r0 + 0][head], ps); atomicAdd(&sa_d[r0 + 0][head], pd);
    ps = acc1.x*as.x + acc1.y*as.y + acc1.z*as.z + acc1.w*as.w;
    pd = acc1.x*ad.x + acc1.y*ad.y + acc1.z*ad.z + acc1.w*ad.w;
    atomicAdd(&sa_s[r0 + 1][head], ps); atomicAdd(&sa_d[r0 + 1][head], pd);
    ps = acc2.x*as.x + acc2.y*as.y + acc2.z*as.z + acc2.w*as.w;
    pd = acc2.x*ad.x + acc2.y*ad.y + acc2.z*ad.z + acc2.w*ad.w;
    atomicAdd(&sa_s[r0 + 2][head], ps); atomicAdd(&sa_d[r0 + 2][head], pd);
    ps = acc3.x*as.x + acc3.y*as.y + acc3.z*as.z + acc3.w*as.w;
    pd = acc3.x*ad.x + acc3.y*ad.y + acc3.z*ad.z + acc3.w*ad.w;
    atomicAdd(&sa_s[r0 + 3][head], ps); atomicAdd(&sa_d[r0 + 3][head], pd);
    __syncthreads();

    if (tid < 96) {
        int r = tid / HEADS, hh = tid - r * HEADS;
        g_asrc[(size_t)(row0 + r) * HEADS + hh] = sa_s[r][hh];
    } else if (tid < 192) {
        int t2 = tid - 96;
        int r = t2 / HEADS, hh = t2 - r * HEADS;
        g_adst[(size_t)(row0 + r) * HEADS + hh] = sa_d[r][hh];
    }
}

// ---------------- K2: e = lrelu(a_src[s]+a_dst[d]); seg-max; degree count ---
__global__ void k_edge1() {
    int i = blockIdx.x * blockDim.x + threadIdx.x;
    if (i >= ETOT) return;
    int s, d;
    if (i < N_EDGES) { s = g_src[i]; d = g_dst[i]; }
    else             { s = i - N_EDGES; d = s; }
    #pragma unroll
    for (int h = 0; h < HEADS; h++) {
        float e = g_asrc[s * HEADS + h] + g_adst[d * HEADS + h];
        e = (e > 0.0f) ? e : NEG_ATT * e;
        g_e[(size_t)i * HEADS + h] = e;
        atomicMax(&g_mkey[d * HEADS + h], fenc(e));
    }
    atomicAdd(&g_deg[d], 1);
}

// ---------------- K3: single-block prefix scan over degrees -----------------
__global__ __launch_bounds__(SCAN_T) void k_scan() {
    __shared__ int sh[SCAN_T];
    int t = threadIdx.x;
    const int chunk = (N_NODES + SCAN_T - 1) / SCAN_T;   // 98
    int b = t * chunk;
    int e = b + chunk; if (e > N_NODES) e = N_NODES;
    int s = 0;
    for (int i = b; i < e; i++) s += g_deg[i];
    sh[t] = s;
    __syncthreads();
    for (int off = 1; off < SCAN_T; off <<= 1) {
        int v = (t >= off) ? sh[t - off] : 0;
        __syncthreads();
        sh[t] += v;
        __syncthreads();
    }
    int run = (t == 0) ? 0 : sh[t - 1];
    for (int i = b; i < e; i++) { g_row[i] = run; run += g_deg[i]; }
    if (t == SCAN_T - 1) g_row[N_NODES] = run;
}

// ---------------- K4: exp(e - m); seg-sum; CSR fill -------------------------
__global__ void k_edge2() {
    int i = blockIdx.x * blockDim.x + threadIdx.x;
    if (i >= ETOT) return;
    int s, d;
    if (i < N_EDGES) { s = g_src[i]; d = g_dst[i]; }
    else             { s = i - N_EDGES; d = s; }
    #pragma unroll
    for (int h = 0; h < HEADS; h++) {
        float m = fdec(g_mkey[d * HEADS + h]);
        float ee = __expf(g_e[(size_t)i * HEADS + h] - m);
        g_e[(size_t)i * HEADS + h] = ee;
        atomicAdd(&g_den[d * HEADS + h], ee);
    }
    int slot = g_row[d] + atomicAdd(&g_cnt[d], 1);
    g_ecol[slot] = s;
    g_eid[slot]  = i;
}

// ---------------- K5: CSR gather aggregate + bias + leaky ReLU --------------
// one block per dst node; 192 threads = one output feature each.
__global__ __launch_bounds__(HIDDEN) void k_agg(const float* __restrict__ bias) {
    int n = blockIdx.x;
    int c = threadIdx.x;
    int beg = g_row[n], end = g_row[n + 1];
    int head = c >> 6;
    float inv = __fdividef(1.0f, g_den[n * HEADS + head]);
    float acc = 0.0f;
    for (int p = beg; p < end; p++) {
        int s = g_ecol[p];
        int e = g_eid[p];
        float ee = g_e[(size_t)e * HEADS + head];
        acc += ee * g_h[(size_t)s * HIDDEN + c];
    }
    float v = acc * inv + bias[c];
    v = (v > 0.0f) ? v : NEG_ACT * v;
    g_out[(size_t)n * HIDDEN + c] = v;
}

// ---------------- K6: sorted-batch max pool (int32 batch!) -------------------
__global__ __launch_bounds__(HIDDEN) void k_pool(const int* __restrict__ batch) {
    int c = threadIdx.x;
    int n0 = blockIdx.x * 64;
    int cur = -1;
    float m = 0.0f;
    for (int n = n0; n < n0 + 64 && n < N_NODES; n++) {
        int bg = batch[n];
        bg = (bg < 0) ? 0 : ((bg >= NUM_GRAPHS) ? NUM_GRAPHS - 1 : bg);
        float v = g_out[(size_t)n * HIDDEN + c];
        if (bg != cur) {
            if (cur >= 0) atomicMax(&g_pool[cur * HIDDEN + c], fenc(m));
            cur = bg; m = v;
        } else {
            m = fmaxf(m, v);
        }
    }
    if (cur >= 0) atomicMax(&g_pool[cur * HIDDEN + c], fenc(m));
}

// ---------------- K7: classifier --------------------------------------------
__global__ void k_cls(const float* __restrict__ cls_W,
                      const float* __restrict__ cls_b,
                      float* __restrict__ out)
{
    int t = threadIdx.x;  // 256 threads: (graph, class)
    int g = t >> 1, c = t & 1;
    float acc = cls_b[c];
    #pragma unroll 8
    for (int k = 0; k < HIDDEN; k++)
        acc += fdec(g_pool[g * HIDDEN + k]) * cls_W[k * NUM_CLASSES + c];
    out[g * NUM_CLASSES + c] = acc;
}

// ---------------- launch ----------------------------------------------------
extern "C" void kernel_launch(void* const* d_in, const int* in_sizes, int n_in,
                              void* d_out, int out_size)
{
    const float* x       = (const float*)d_in[0];
    const int*   ei      = (const int*)d_in[1];     // int64 in reference -> int32 in harness
    const int*   batch   = (const int*)d_in[2];     // likewise
    const float* W       = (const float*)d_in[3];
    const float* att_src = (const float*)d_in[4];
    const float* att_dst = (const float*)d_in[5];
    const float* bias    = (const float*)d_in[6];
    const float* cls_W   = (const float*)d_in[7];
    const float* cls_b   = (const float*)d_in[8];
    float* out = (float*)d_out;

    k_init<<<(N_EDGES + 255) / 256, 256>>>(ei);
    k_gemm<<<N_NODES / 32, dim3(48, 8)>>>(x, W, att_src, att_dst);
    k_edge1<<<(ETOT + 255) / 256, 256>>>();
    k_scan<<<1, SCAN_T>>>();
    k_edge2<<<(ETOT + 255) / 256, 256>>>();
    k_agg<<<N_NODES, HIDDEN>>>(bias);
    k_pool<<<(N_NODES + 63) / 64, HIDDEN>>>(batch);
    k_cls<<<1, 256>>>(cls_W, cls_b, out);
}

// round 8
// speedup vs baseline: 1.2442x; 1.2442x over previous
#include <cuda_runtime.h>
#include <cuda_bf16.h>
#include <limits.h>

#define N_NODES   100000
#define N_EDGES   1600000
#define ETOT      (N_EDGES + N_NODES)
#define F_IN      100
#define HEADS     3
#define HEAD_DIM  64
#define HIDDEN    192
#define NUM_GRAPHS 128
#define NUM_CLASSES 2
#define NEG_ATT   0.2f
#define NEG_ACT   0.01f
#define SCAN_B    1024
#define SCAN_NB   ((N_NODES + SCAN_B - 1) / SCAN_B)   // 98

// ---------------- scratch (device globals; no allocations allowed) ----------
__device__ __align__(16) float g_h   [(size_t)N_NODES * HIDDEN];   // 76.8 MB
__device__ __align__(16) float g_out [(size_t)N_NODES * HIDDEN];   // 76.8 MB
__device__ __align__(16) float g_asrc[N_NODES * HEADS];
__device__ __align__(16) float g_adst[N_NODES * HEADS];
__device__ __align__(16) int   g_mkey[N_NODES * HEADS];            // encoded float max
__device__ __align__(16) float g_den [N_NODES * HEADS];
__device__ __align__(16) float g_e   [(size_t)ETOT * HEADS];       // 20.4 MB (staging)
__device__ __align__(16) int   g_src [N_EDGES];
__device__ __align__(16) int   g_dst [N_EDGES];
__device__ __align__(16) int   g_pool[NUM_GRAPHS * HIDDEN];        // encoded float max
// CSR structures
__device__ __align__(16) int   g_deg [N_NODES];
__device__ __align__(16) int   g_cnt [N_NODES];
__device__ __align__(16) int   g_row [N_NODES + 1];
__device__ __align__(16) int   g_ecol[ETOT];                       // src per CSR slot
__device__ __align__(16) float g_ew  [HEADS][ETOT];                // exp weights per slot
__device__ __align__(16) int   g_bsum[SCAN_NB];
__device__ __align__(16) int   g_boff[SCAN_NB];

// monotone float<->int encoding so atomicMax(int) == float max (finite vals)
__device__ __forceinline__ int fenc(float f) {
    int i = __float_as_int(f);
    return i >= 0 ? i : (i ^ 0x7FFFFFFF);
}
__device__ __forceinline__ float fdec(int i) {
    return __int_as_float(i >= 0 ? i : (i ^ 0x7FFFFFFF));
}
__device__ __forceinline__ int clampN(int v) {
    return (v < 0) ? 0 : ((v >= N_NODES) ? N_NODES - 1 : v);
}

// ---------------- K0: init + edge index load (int32 inputs) ------------------
__global__ void k_init(const int* __restrict__ ei) {
    int i = blockIdx.x * blockDim.x + threadIdx.x;
    if (i < N_NODES * HEADS) { g_mkey[i] = INT_MIN; g_den[i] = 0.0f; }
    if (i < N_NODES) { g_deg[i] = 0; g_cnt[i] = 0; }
    if (i < NUM_GRAPHS * HIDDEN) g_pool[i] = INT_MIN;
    if (i < N_EDGES) {
        g_src[i] = clampN(ei[i]);
        g_dst[i] = clampN(ei[N_EDGES + i]);
    }
}

// ---------------- K1: h = x @ W, fused a_src/a_dst epilogue ------------------
__global__ __launch_bounds__(384) void k_gemm(
    const float* __restrict__ x, const float* __restrict__ W,
    const float* __restrict__ att_src, const float* __restrict__ att_dst)
{
    __shared__ float xs[32][F_IN + 4];
    __shared__ float sa_s[32][HEADS];
    __shared__ float sa_d[32][HEADS];

    const int tx = threadIdx.x;           // 0..47  (col group)
    const int ty = threadIdx.y;           // 0..7   (row group of 4)
    const int tid = ty * 48 + tx;
    const int row0 = blockIdx.x * 32;

    for (int t = tid; t < 32 * F_IN; t += 384) {
        int r = t / F_IN, k = t - r * F_IN;
        xs[r][k] = x[(size_t)(row0 + r) * F_IN + k];
    }
    if (tid < 96)  ((float*)sa_s)[tid] = 0.0f;
    else if (tid < 192) ((float*)sa_d)[tid - 96] = 0.0f;
    __syncthreads();

    float4 acc0 = {0,0,0,0}, acc1 = {0,0,0,0}, acc2 = {0,0,0,0}, acc3 = {0,0,0,0};
    const int r0 = ty * 4;
    const float4* W4 = (const float4*)W;  // [F_IN][48] float4

    #pragma unroll 4
    for (int k = 0; k < F_IN; k++) {
        float4 w = __ldg(&W4[k * 48 + tx]);
        float x0 = xs[r0 + 0][k], x1 = xs[r0 + 1][k], x2 = xs[r0 + 2][k], x3 = xs[r0 + 3][k];
        acc0.x += x0 * w.x; acc0.y += x0 * w.y; acc0.z += x0 * w.z; acc0.w += x0 * w.w;
        acc1.x += x1 * w.x; acc1.y += x1 * w.y; acc1.z += x1 * w.z; acc1.w += x1 * w.w;
        acc2.x += x2 * w.x; acc2.y += x2 * w.y; acc2.z += x2 * w.z; acc2.w += x2 * w.w;
        acc3.x += x3 * w.x; acc3.y += x3 * w.y; acc3.z += x3 * w.z; acc3.w += x3 * w.w;
    }

    float4* H4 = (float4*)g_h;
    H4[(size_t)(row0 + r0 + 0) * 48 + tx] = acc0;
    H4[(size_t)(row0 + r0 + 1) * 48 + tx] = acc1;
    H4[(size_t)(row0 + r0 + 2) * 48 + tx] = acc2;
    H4[(size_t)(row0 + r0 + 3) * 48 + tx] = acc3;

    const int head = tx >> 4;
    float4 as = __ldg(&((const float4*)att_src)[tx]);
    float4 ad = __ldg(&((const float4*)att_dst)[tx]);
    float ps, pd;
    ps = acc0.x*as.x + acc0.y*as.y + acc0.z*as.z + acc0.w*as.w;
    pd = acc0.x*ad.x + acc0.y*ad.y + acc0.z*ad.z + acc0.w*ad.w;
    atomicAdd(&sa_s[r0 + 0][head], ps); atomicAdd(&sa_d[r0 + 0][head], pd);
    ps = acc1.x*as.x + acc1.y*as.y + acc1.z*as.z + acc1.w*as.w;
    pd = acc1.x*ad.x + acc1.y*ad.y + acc1.z*ad.z + acc1.w*ad.w;
    atomicAdd(&sa_s[r0 + 1][head], ps); atomicAdd(&sa_d[r0 + 1][head], pd);
    ps = acc2.x*as.x + acc2.y*as.y + acc2.z*as.z + acc2.w*as.w;
    pd = acc2.x*ad.x + acc2.y*ad.y + acc2.z*ad.z + acc2.w*ad.w;
    atomicAdd(&sa_s[r0 + 2][head], ps); atomicAdd(&sa_d[r0 + 2][head], pd);
    ps = acc3.x*as.x + acc3.y*as.y + acc3.z*as.z + acc3.w*as.w;
    pd = acc3.x*ad.x + acc3.y*ad.y + acc3.z*ad.z + acc3.w*ad.w;
    atomicAdd(&sa_s[r0 + 3][head], ps); atomicAdd(&sa_d[r0 + 3][head], pd);
    __syncthreads();

    if (tid < 96) {
        int r = tid / HEADS, hh = tid - r * HEADS;
        g_asrc[(size_t)(row0 + r) * HEADS + hh] = sa_s[r][hh];
    } else if (tid < 192) {
        int t2 = tid - 96;
        int r = t2 / HEADS, hh = t2 - r * HEADS;
        g_adst[(size_t)(row0 + r) * HEADS + hh] = sa_d[r][hh];
    }
}

// ---------------- K2: e = lrelu(a_src[s]+a_dst[d]); seg-max; degree ---------
__global__ void k_edge1() {
    int i = blockIdx.x * blockDim.x + threadIdx.x;
    if (i >= ETOT) return;
    int s, d;
    if (i < N_EDGES) { s = g_src[i]; d = g_dst[i]; }
    else             { s = i - N_EDGES; d = s; }
    #pragma unroll
    for (int h = 0; h < HEADS; h++) {
        float e = g_asrc[s * HEADS + h] + g_adst[d * HEADS + h];
        e = (e > 0.0f) ? e : NEG_ATT * e;
        g_e[(size_t)i * HEADS + h] = e;
        atomicMax(&g_mkey[d * HEADS + h], fenc(e));
    }
    atomicAdd(&g_deg[d], 1);
}

// ---------------- K3a/b/c: multi-block prefix scan over degrees -------------
__global__ __launch_bounds__(SCAN_B) void k_scan1() {
    __shared__ int sh[SCAN_B];
    int t = threadIdx.x;
    int i = blockIdx.x * SCAN_B + t;
    int v = (i < N_NODES) ? g_deg[i] : 0;
    sh[t] = v;
    __syncthreads();
    #pragma unroll
    for (int off = 1; off < SCAN_B; off <<= 1) {
        int u = (t >= off) ? sh[t - off] : 0;
        __syncthreads();
        sh[t] += u;
        __syncthreads();
    }
    if (i <= N_NODES) { /* exclusive value */ }
    if (i < N_NODES) g_row[i] = sh[t] - v;      // exclusive within block
    if (t == SCAN_B - 1) g_bsum[blockIdx.x] = sh[t];
}
__global__ void k_scan2() {
    __shared__ int sh[SCAN_NB];
    int t = threadIdx.x;                        // SCAN_NB threads
    int v = g_bsum[t];
    sh[t] = v;
    __syncthreads();
    for (int off = 1; off < SCAN_NB; off <<= 1) {
        int u = (t >= off) ? sh[t - off] : 0;
        __syncthreads();
        sh[t] += u;
        __syncthreads();
    }
    g_boff[t] = sh[t] - v;                      // exclusive block offset
    if (t == SCAN_NB - 1) g_row[N_NODES] = sh[t];
}
__global__ __launch_bounds__(SCAN_B) void k_scan3() {
    int i = blockIdx.x * SCAN_B + threadIdx.x;
    if (i < N_NODES) g_row[i] += g_boff[blockIdx.x];
}

// ---------------- K4: exp(e - m); seg-sum; CSR fill (weights in-slot) -------
__global__ void k_edge2() {
    int i = blockIdx.x * blockDim.x + threadIdx.x;
    if (i >= ETOT) return;
    int s, d;
    if (i < N_EDGES) { s = g_src[i]; d = g_dst[i]; }
    else             { s = i - N_EDGES; d = s; }
    int slot = g_row[d] + atomicAdd(&g_cnt[d], 1);
    g_ecol[slot] = s;
    #pragma unroll
    for (int h = 0; h < HEADS; h++) {
        float m = fdec(g_mkey[d * HEADS + h]);
        float ee = __expf(g_e[(size_t)i * HEADS + h] - m);
        g_ew[h][slot] = ee;
        atomicAdd(&g_den[d * HEADS + h], ee);
    }
}

// ---------------- K5: CSR gather aggregate + bias + leaky ReLU --------------
// one block per dst node; 192 threads = one output feature each.
__global__ __launch_bounds__(HIDDEN) void k_agg(const float* __restrict__ bias) {
    int n = blockIdx.x;
    int c = threadIdx.x;
    int beg = g_row[n], end = g_row[n + 1];
    int head = c >> 6;
    float inv = __fdividef(1.0f, g_den[n * HEADS + head]);
    float acc = 0.0f;
    for (int p = beg; p < end; p++) {
        int s = g_ecol[p];
        float ee = g_ew[head][p];
        acc += ee * g_h[(size_t)s * HIDDEN + c];
    }
    float v = acc * inv + bias[c];
    v = (v > 0.0f) ? v : NEG_ACT * v;
    g_out[(size_t)n * HIDDEN + c] = v;
}

// ---------------- K6: sorted-batch max pool ---------------------------------
__global__ __launch_bounds__(HIDDEN) void k_pool(const int* __restrict__ batch) {
    int c = threadIdx.x;
    int n0 = blockIdx.x * 64;
    int cur = -1;
    float m = 0.0f;
    for (int n = n0; n < n0 + 64 && n < N_NODES; n++) {
        int bg = batch[n];
        bg = (bg < 0) ? 0 : ((bg >= NUM_GRAPHS) ? NUM_GRAPHS - 1 : bg);
        float v = g_out[(size_t)n * HIDDEN + c];
        if (bg != cur) {
            if (cur >= 0) atomicMax(&g_pool[cur * HIDDEN + c], fenc(m));
            cur = bg; m = v;
        } else {
            m = fmaxf(m, v);
        }
    }
    if (cur >= 0) atomicMax(&g_pool[cur * HIDDEN + c], fenc(m));
}

// ---------------- K7: classifier --------------------------------------------
__global__ void k_cls(const float* __restrict__ cls_W,
                      const float* __restrict__ cls_b,
                      float* __restrict__ out)
{
    int t = threadIdx.x;  // 256 threads: (graph, class)
    int g = t >> 1, c = t & 1;
    float acc = cls_b[c];
    #pragma unroll 8
    for (int k = 0; k < HIDDEN; k++)
        acc += fdec(g_pool[g * HIDDEN + k]) * cls_W[k * NUM_CLASSES + c];
    out[g * NUM_CLASSES + c] = acc;
}

// ---------------- launch ----------------------------------------------------
extern "C" void kernel_launch(void* const* d_in, const int* in_sizes, int n_in,
                              void* d_out, int out_size)
{
    const float* x       = (const float*)d_in[0];
    const int*   ei      = (const int*)d_in[1];
    const int*   batch   = (const int*)d_in[2];
    const float* W       = (const float*)d_in[3];
    const float* att_src = (const float*)d_in[4];
    const float* att_dst = (const float*)d_in[5];
    const float* bias    = (const float*)d_in[6];
    const float* cls_W   = (const float*)d_in[7];
    const float* cls_b   = (const float*)d_in[8];
    float* out = (float*)d_out;

    k_init<<<(N_EDGES + 255) / 256, 256>>>(ei);
    k_gemm<<<N_NODES / 32, dim3(48, 8)>>>(x, W, att_src, att_dst);
    k_edge1<<<(ETOT + 255) / 256, 256>>>();
    k_scan1<<<SCAN_NB, SCAN_B>>>();
    k_scan2<<<1, SCAN_NB>>>();
    k_scan3<<<SCAN_NB, SCAN_B>>>();
    k_edge2<<<(ETOT + 255) / 256, 256>>>();
    k_agg<<<N_NODES, HIDDEN>>>(bias);
    k_pool<<<(N_NODES + 63) / 64, HIDDEN>>>(batch);
    k_cls<<<1, 256>>>(cls_W, cls_b, out);
}

// round 9
// speedup vs baseline: 1.4029x; 1.1275x over previous
#include <cuda_runtime.h>
#include <cuda_bf16.h>
#include <limits.h>

#define N_NODES   100000
#define N_EDGES   1600000
#define ETOT      (N_EDGES + N_NODES)
#define F_IN      100
#define HEADS     3
#define HEAD_DIM  64
#define HIDDEN    192
#define NUM_GRAPHS 128
#define NUM_CLASSES 2
#define NEG_ATT   0.2f
#define NEG_ACT   0.01f
#define SCAN_B    1024
#define SCAN_NB   ((N_NODES + SCAN_B - 1) / SCAN_B)   // 98

// ---------------- scratch (device globals; no allocations allowed) ----------
__device__ __align__(16) float g_h    [(size_t)N_NODES * HIDDEN];   // 76.8 MB
__device__ __align__(16) float g_out  [(size_t)N_NODES * HIDDEN];   // 76.8 MB
__device__ __align__(16) float g_asrc4[(size_t)N_NODES * 4];        // padded logits
__device__ __align__(16) float g_adst4[(size_t)N_NODES * 4];
__device__ __align__(16) int   g_src  [N_EDGES];
__device__ __align__(16) int   g_dst  [N_EDGES];
__device__ __align__(16) int   g_pool [NUM_GRAPHS * HIDDEN];        // encoded float max
// CSR structures
__device__ __align__(16) int    g_deg [N_NODES];
__device__ __align__(16) int    g_cnt [N_NODES];
__device__ __align__(16) int    g_row [N_NODES + 1];
__device__ __align__(16) int    g_ecol[ETOT];                       // src per CSR slot
__device__ __align__(16) float4 g_ew4 [ETOT];                       // (ee0,ee1,ee2,0)
__device__ __align__(16) int    g_bsum[SCAN_NB];
__device__ __align__(16) int    g_boff[SCAN_NB];

// monotone float<->int encoding so atomicMax(int) == float max (finite vals)
__device__ __forceinline__ int fenc(float f) {
    int i = __float_as_int(f);
    return i >= 0 ? i : (i ^ 0x7FFFFFFF);
}
__device__ __forceinline__ float fdec(int i) {
    return __int_as_float(i >= 0 ? i : (i ^ 0x7FFFFFFF));
}
__device__ __forceinline__ int clampN(int v) {
    return (v < 0) ? 0 : ((v >= N_NODES) ? N_NODES - 1 : v);
}

// ---------------- K0: init + edge index load (int32 inputs) ------------------
__global__ void k_init(const int* __restrict__ ei) {
    int i = blockIdx.x * blockDim.x + threadIdx.x;
    if (i < N_NODES) { g_deg[i] = 0; g_cnt[i] = 0; }
    if (i < NUM_GRAPHS * HIDDEN) g_pool[i] = INT_MIN;
    if (i < N_EDGES) {
        g_src[i] = clampN(ei[i]);
        g_dst[i] = clampN(ei[N_EDGES + i]);
    }
}

// ---------------- K1: h = x @ W, fused a_src/a_dst epilogue ------------------
// block: 48 x 8 threads; 32 rows per block; thread = 4 cols (float4) x 4 rows
__global__ __launch_bounds__(384) void k_gemm(
    const float* __restrict__ x, const float* __restrict__ W,
    const float* __restrict__ att_src, const float* __restrict__ att_dst)
{
    __shared__ float xs[32][F_IN + 4];
    __shared__ float sa_s[32][HEADS];
    __shared__ float sa_d[32][HEADS];

    const int tx = threadIdx.x;           // 0..47
    const int ty = threadIdx.y;           // 0..7
    const int tid = ty * 48 + tx;
    const int row0 = blockIdx.x * 32;

    for (int t = tid; t < 32 * F_IN; t += 384) {
        int r = t / F_IN, k = t - r * F_IN;
        xs[r][k] = x[(size_t)(row0 + r) * F_IN + k];
    }
    if (tid < 96)  ((float*)sa_s)[tid] = 0.0f;
    else if (tid < 192) ((float*)sa_d)[tid - 96] = 0.0f;
    __syncthreads();

    float4 acc0 = {0,0,0,0}, acc1 = {0,0,0,0}, acc2 = {0,0,0,0}, acc3 = {0,0,0,0};
    const int r0 = ty * 4;
    const float4* W4 = (const float4*)W;  // [F_IN][48] float4

    #pragma unroll 4
    for (int k = 0; k < F_IN; k++) {
        float4 w = __ldg(&W4[k * 48 + tx]);
        float x0 = xs[r0 + 0][k], x1 = xs[r0 + 1][k], x2 = xs[r0 + 2][k], x3 = xs[r0 + 3][k];
        acc0.x += x0 * w.x; acc0.y += x0 * w.y; acc0.z += x0 * w.z; acc0.w += x0 * w.w;
        acc1.x += x1 * w.x; acc1.y += x1 * w.y; acc1.z += x1 * w.z; acc1.w += x1 * w.w;
        acc2.x += x2 * w.x; acc2.y += x2 * w.y; acc2.z += x2 * w.z; acc2.w += x2 * w.w;
        acc3.x += x3 * w.x; acc3.y += x3 * w.y; acc3.z += x3 * w.z; acc3.w += x3 * w.w;
    }

    float4* H4 = (float4*)g_h;
    H4[(size_t)(row0 + r0 + 0) * 48 + tx] = acc0;
    H4[(size_t)(row0 + r0 + 1) * 48 + tx] = acc1;
    H4[(size_t)(row0 + r0 + 2) * 48 + tx] = acc2;
    H4[(size_t)(row0 + r0 + 3) * 48 + tx] = acc3;

    const int head = tx >> 4;
    float4 as = __ldg(&((const float4*)att_src)[tx]);
    float4 ad = __ldg(&((const float4*)att_dst)[tx]);
    float ps, pd;
    ps = acc0.x*as.x + acc0.y*as.y + acc0.z*as.z + acc0.w*as.w;
    pd = acc0.x*ad.x + acc0.y*ad.y + acc0.z*ad.z + acc0.w*ad.w;
    atomicAdd(&sa_s[r0 + 0][head], ps); atomicAdd(&sa_d[r0 + 0][head], pd);
    ps = acc1.x*as.x + acc1.y*as.y + acc1.z*as.z + acc1.w*as.w;
    pd = acc1.x*ad.x + acc1.y*ad.y + acc1.z*ad.z + acc1.w*ad.w;
    atomicAdd(&sa_s[r0 + 1][head], ps); atomicAdd(&sa_d[r0 + 1][head], pd);
    ps = acc2.x*as.x + acc2.y*as.y + acc2.z*as.z + acc2.w*as.w;
    pd = acc2.x*ad.x + acc2.y*ad.y + acc2.z*ad.z + acc2.w*ad.w;
    atomicAdd(&sa_s[r0 + 2][head], ps); atomicAdd(&sa_d[r0 + 2][head], pd);
    ps = acc3.x*as.x + acc3.y*as.y + acc3.z*as.z + acc3.w*as.w;
    pd = acc3.x*ad.x + acc3.y*ad.y + acc3.z*ad.z + acc3.w*ad.w;
    atomicAdd(&sa_s[r0 + 3][head], ps); atomicAdd(&sa_d[r0 + 3][head], pd);
    __syncthreads();

    // padded float4 stores: one aligned sector per node record
    if (tid < 128) {
        int r = tid >> 2, q = tid & 3;
        g_asrc4[(size_t)(row0 + r) * 4 + q] = (q < HEADS) ? sa_s[r][q] : 0.0f;
    } else if (tid < 256) {
        int t2 = tid - 128;
        int r = t2 >> 2, q = t2 & 3;
        g_adst4[(size_t)(row0 + r) * 4 + q] = (q < HEADS) ? sa_d[r][q] : 0.0f;
    }
}

// ---------------- K2: degree count ------------------------------------------
__global__ void k_deg() {
    int i = blockIdx.x * blockDim.x + threadIdx.x;
    if (i >= ETOT) return;
    int d = (i < N_EDGES) ? g_dst[i] : (i - N_EDGES);
    atomicAdd(&g_deg[d], 1);
}

// ---------------- K3a/b/c: multi-block prefix scan over degrees -------------
__global__ __launch_bounds__(SCAN_B) void k_scan1() {
    __shared__ int sh[SCAN_B];
    int t = threadIdx.x;
    int i = blockIdx.x * SCAN_B + t;
    int v = (i < N_NODES) ? g_deg[i] : 0;
    sh[t] = v;
    __syncthreads();
    #pragma unroll
    for (int off = 1; off < SCAN_B; off <<= 1) {
        int u = (t >= off) ? sh[t - off] : 0;
        __syncthreads();
        sh[t] += u;
        __syncthreads();
    }
    if (i < N_NODES) g_row[i] = sh[t] - v;      // exclusive within block
    if (t == SCAN_B - 1) g_bsum[blockIdx.x] = sh[t];
}
__global__ void k_scan2() {
    __shared__ int sh[SCAN_NB];
    int t = threadIdx.x;                        // SCAN_NB threads
    int v = g_bsum[t];
    sh[t] = v;
    __syncthreads();
    for (int off = 1; off < SCAN_NB; off <<= 1) {
        int u = (t >= off) ? sh[t - off] : 0;
        __syncthreads();
        sh[t] += u;
        __syncthreads();
    }
    g_boff[t] = sh[t] - v;
    if (t == SCAN_NB - 1) g_row[N_NODES] = sh[t];
}
__global__ __launch_bounds__(SCAN_B) void k_scan3() {
    int i = blockIdx.x * SCAN_B + threadIdx.x;
    if (i < N_NODES) g_row[i] += g_boff[blockIdx.x];
}

// ---------------- K4: attention weights + CSR fill (no max, no den atomics) -
__global__ void k_edge2() {
    int i = blockIdx.x * blockDim.x + threadIdx.x;
    if (i >= ETOT) return;
    int s, d;
    if (i < N_EDGES) { s = g_src[i]; d = g_dst[i]; }
    else             { s = i - N_EDGES; d = s; }
    int slot = g_row[d] + atomicAdd(&g_cnt[d], 1);
    float4 A = *(const float4*)&g_asrc4[(size_t)s * 4];
    float4 B = *(const float4*)&g_adst4[(size_t)d * 4];
    float e0 = A.x + B.x, e1 = A.y + B.y, e2 = A.z + B.z;
    e0 = (e0 > 0.0f) ? e0 : NEG_ATT * e0;
    e1 = (e1 > 0.0f) ? e1 : NEG_ATT * e1;
    e2 = (e2 > 0.0f) ? e2 : NEG_ATT * e2;
    g_ecol[slot] = s;
    g_ew4[slot] = make_float4(__expf(e0), __expf(e1), __expf(e2), 0.0f);
}

// ---------------- K5: CSR gather + inline denominator + bias + leaky --------
// one block per dst node; 192 threads = one output feature each.
__global__ __launch_bounds__(HIDDEN) void k_agg(const float* __restrict__ bias) {
    int n = blockIdx.x;
    int c = threadIdx.x;
    int beg = g_row[n], end = g_row[n + 1];
    int head = c >> 6;
    const float* ew = (const float*)g_ew4;
    float acc = 0.0f, den = 0.0f;
    for (int p = beg; p < end; p++) {
        int s = g_ecol[p];
        float ee = ew[(size_t)p * 4 + head];
        den += ee;
        acc += ee * g_h[(size_t)s * HIDDEN + c];
    }
    float v = __fdividef(acc, den) + bias[c];
    v = (v > 0.0f) ? v : NEG_ACT * v;
    g_out[(size_t)n * HIDDEN + c] = v;
}

// ---------------- K6: sorted-batch max pool ---------------------------------
__global__ __launch_bounds__(HIDDEN) void k_pool(const int* __restrict__ batch) {
    int c = threadIdx.x;
    int n0 = blockIdx.x * 64;
    int cur = -1;
    float m = 0.0f;
    for (int n = n0; n < n0 + 64 && n < N_NODES; n++) {
        int bg = batch[n];
        bg = (bg < 0) ? 0 : ((bg >= NUM_GRAPHS) ? NUM_GRAPHS - 1 : bg);
        float v = g_out[(size_t)n * HIDDEN + c];
        if (bg != cur) {
            if (cur >= 0) atomicMax(&g_pool[cur * HIDDEN + c], fenc(m));
            cur = bg; m = v;
        } else {
            m = fmaxf(m, v);
        }
    }
    if (cur >= 0) atomicMax(&g_pool[cur * HIDDEN + c], fenc(m));
}

// ---------------- K7: classifier --------------------------------------------
__global__ void k_cls(const float* __restrict__ cls_W,
                      const float* __restrict__ cls_b,
                      float* __restrict__ out)
{
    int t = threadIdx.x;  // 256 threads: (graph, class)
    int g = t >> 1, c = t & 1;
    float acc = cls_b[c];
    #pragma unroll 8
    for (int k = 0; k < HIDDEN; k++)
        acc += fdec(g_pool[g * HIDDEN + k]) * cls_W[k * NUM_CLASSES + c];
    out[g * NUM_CLASSES + c] = acc;
}

// ---------------- launch ----------------------------------------------------
extern "C" void kernel_launch(void* const* d_in, const int* in_sizes, int n_in,
                              void* d_out, int out_size)
{
    const float* x       = (const float*)d_in[0];
    const int*   ei      = (const int*)d_in[1];
    const int*   batch   = (const int*)d_in[2];
    const float* W       = (const float*)d_in[3];
    const float* att_src = (const float*)d_in[4];
    const float* att_dst = (const float*)d_in[5];
    const float* bias    = (const float*)d_in[6];
    const float* cls_W   = (const float*)d_in[7];
    const float* cls_b   = (const float*)d_in[8];
    float* out = (float*)d_out;

    k_init<<<(N_EDGES + 255) / 256, 256>>>(ei);
    k_gemm<<<N_NODES / 32, dim3(48, 8)>>>(x, W, att_src, att_dst);
    k_deg<<<(ETOT + 255) / 256, 256>>>();
    k_scan1<<<SCAN_NB, SCAN_B>>>();
    k_scan2<<<1, SCAN_NB>>>();
    k_scan3<<<SCAN_NB, SCAN_B>>>();
    k_edge2<<<(ETOT + 255) / 256, 256>>>();
    k_agg<<<N_NODES, HIDDEN>>>(bias);
    k_pool<<<(N_NODES + 63) / 64, HIDDEN>>>(batch);
    k_cls<<<1, 256>>>(cls_W, cls_b, out);
}